// round 7
// baseline (speedup 1.0000x reference)
#include <cuda_runtime.h>
#include <cuda_bf16.h>
#include <cstdint>

#define SCALE 0.125f
#define LOG2E 1.4426950408889634f
#define SWZ128(o) ((o) ^ (((o) >> 3) & 0x70))

// ---------------- scratch (alloc-free rule: module-level device globals) ----
__device__ __nv_bfloat16 g_xs[25165824];     // 8192 x 3072  x split  [Ah|Ah|Al]
__device__ __nv_bfloat16 g_ws[9437184];      // 3072 x 3072  w_qkv split [Bh|Bl|Bh]
__device__ __nv_bfloat16 g_wp[3145728];      // 1024 x 3072  w_proj split
__device__ __nv_bfloat16 g_aos[25165824];    // 8192 x 3072  attn-out split [Ah|Ah|Al]
__device__ __nv_bfloat16 g_qkvh[25165824];   // 8192 x 3072  qkv hi bf16
__device__ __nv_bfloat16 g_qkvl[25165824];   // 8192 x 3072  qkv lo bf16

// ---------------- helpers ----------------
__device__ __forceinline__ uint32_t smem_u32(const void* p) {
    uint32_t a;
    asm("{ .reg .u64 t; cvta.to.shared.u64 t, %1; cvt.u32.u64 %0, t; }" : "=r"(a) : "l"(p));
    return a;
}
__device__ __forceinline__ void ldsm4(uint32_t& r0, uint32_t& r1, uint32_t& r2,
                                      uint32_t& r3, uint32_t a) {
    asm volatile("ldmatrix.sync.aligned.m8n8.x4.shared.b16 {%0,%1,%2,%3},[%4];"
                 : "=r"(r0), "=r"(r1), "=r"(r2), "=r"(r3) : "r"(a));
}
__device__ __forceinline__ void ldsm4t(uint32_t& r0, uint32_t& r1, uint32_t& r2,
                                       uint32_t& r3, uint32_t a) {
    asm volatile("ldmatrix.sync.aligned.m8n8.x4.trans.shared.b16 {%0,%1,%2,%3},[%4];"
                 : "=r"(r0), "=r"(r1), "=r"(r2), "=r"(r3) : "r"(a));
}
__device__ __forceinline__ void sts128(uint32_t a, uint4 v) {
    asm volatile("st.shared.v4.b32 [%0], {%1,%2,%3,%4};"
                 :: "r"(a), "r"(v.x), "r"(v.y), "r"(v.z), "r"(v.w) : "memory");
}
__device__ __forceinline__ void cpa16(uint32_t dst, const void* src) {
    asm volatile("cp.async.cg.shared.global [%0], [%1], 16;" :: "r"(dst), "l"(src)
                 : "memory");
}
#define CP_COMMIT() asm volatile("cp.async.commit_group;" ::: "memory")
#define CP_WAIT0()  asm volatile("cp.async.wait_group 0;" ::: "memory")
__device__ __forceinline__ void mma16816(float* c, const uint32_t* a,
                                         uint32_t b0, uint32_t b1) {
    asm volatile(
        "mma.sync.aligned.m16n8k16.row.col.f32.bf16.bf16.f32 "
        "{%0,%1,%2,%3},{%4,%5,%6,%7},{%8,%9},{%0,%1,%2,%3};"
        : "+f"(c[0]), "+f"(c[1]), "+f"(c[2]), "+f"(c[3])
        : "r"(a[0]), "r"(a[1]), "r"(a[2]), "r"(a[3]), "r"(b0), "r"(b1));
}
__device__ __forceinline__ uint32_t cvt2(float f0, float f1) {
    uint32_t r;
    asm("cvt.rn.bf16x2.f32 %0, %1, %2;" : "=r"(r) : "f"(f1), "f"(f0));
    return r;
}
__device__ __forceinline__ void mkfrag(uint32_t& h, uint32_t& l, float f0, float f1) {
    h = cvt2(f0, f1);
    float r0 = f0 - __uint_as_float(h << 16);
    float r1 = f1 - __uint_as_float(h & 0xffff0000u);
    l = cvt2(r0, r1);
}

// ---------------- split kernels: f32 -> [hi|hi|lo] or [hi|lo|hi] bf16 --------
__device__ __forceinline__ void split_core(const float* __restrict__ src,
                                           __nv_bfloat16* __restrict__ dst,
                                           bool bpat) {
    long i = (long)blockIdx.x * 256 + threadIdx.x;
    long r = i >> 9;
    int k2 = (int)(i & 511) << 1;
    float2 v = *(const float2*)(src + r * 1024 + k2);
    __nv_bfloat16 h0 = __float2bfloat16(v.x), h1 = __float2bfloat16(v.y);
    __nv_bfloat16 l0 = __float2bfloat16(v.x - __bfloat162float(h0));
    __nv_bfloat16 l1 = __float2bfloat16(v.y - __bfloat162float(h1));
    __nv_bfloat162 hh = __halves2bfloat162(h0, h1);
    __nv_bfloat162 ll = __halves2bfloat162(l0, l1);
    __nv_bfloat16* base = dst + r * 3072 + k2;
    *(__nv_bfloat162*)(base) = hh;
    *(__nv_bfloat162*)(base + 1024) = bpat ? ll : hh;
    *(__nv_bfloat162*)(base + 2048) = bpat ? hh : ll;
}
__global__ __launch_bounds__(256) void k_split_x(const float* __restrict__ s) {
    split_core(s, g_xs, false);
}
__global__ __launch_bounds__(256) void k_split_wqkv(const float* __restrict__ s) {
    split_core(s, g_ws, true);
}
__global__ __launch_bounds__(256) void k_split_wproj(const float* __restrict__ s) {
    split_core(s, g_wp, true);
}

// ---------------- mma.sync GEMM, BK=64, 2-stage, 1 sync/iter -----------------
template <bool SPLIT_OUT, bool HAS_BIAS, int NCOL>
__device__ __forceinline__ void gemm_core(const __nv_bfloat16* __restrict__ A,
                                          const __nv_bfloat16* __restrict__ B,
                                          float* __restrict__ C,
                                          __nv_bfloat16* __restrict__ Ch,
                                          __nv_bfloat16* __restrict__ Cl,
                                          const float* __restrict__ bias,
                                          int bm0) {
    constexpr int KT = 3072;
    constexpr int STG = 32768;
    extern __shared__ char smraw[];
    const uint32_t base = (smem_u32(smraw) + 1023u) & ~1023u;
    const int tid = threadIdx.x, lane = tid & 31, wid = tid >> 5;
    const int wr = wid >> 2, wc = wid & 3;
    const int bm = bm0 + blockIdx.y * 128, bn = blockIdx.x * 128;

    float acc[4][4][4];
#pragma unroll
    for (int i = 0; i < 4; i++)
#pragma unroll
        for (int j = 0; j < 4; j++)
#pragma unroll
            for (int q = 0; q < 4; q++) acc[i][j][q] = 0.f;

    const int lr = tid >> 3, lc8 = tid & 7;
    const __nv_bfloat16* Ap = A + (size_t)(bm + lr) * KT + lc8 * 8;
    const __nv_bfloat16* Bp = B + (size_t)(bn + lr) * KT + lc8 * 8;

#define GEMM_LOAD(stage, it)                                                    \
    do {                                                                        \
        const int _k0 = (it) * 64;                                              \
        const uint32_t _sa = base + (stage) * STG;                              \
        const uint32_t _sb = _sa + 16384;                                       \
        _Pragma("unroll")                                                       \
        for (int _j = 0; _j < 4; _j++) {                                        \
            const uint32_t _d = SWZ128((uint32_t)((lr + _j * 32) * 128 + lc8 * 16)); \
            cpa16(_sa + _d, Ap + (size_t)_j * 32 * KT + _k0);                   \
            cpa16(_sb + _d, Bp + (size_t)_j * 32 * KT + _k0);                   \
        }                                                                       \
    } while (0)

    GEMM_LOAD(0, 0); CP_COMMIT();

    const int arow = wr * 64 + (lane & 15);
    const int aoff = (lane & 16) ? 8 : 0;
    const int brow = wc * 32 + (lane & 7) + ((lane & 16) ? 8 : 0);
    const int boff = (lane & 8) ? 8 : 0;

    for (int it = 0; it < 48; it++) {
        CP_WAIT0();
        __syncthreads();
        if (it + 1 < 48) { GEMM_LOAD((it + 1) & 1, it + 1); CP_COMMIT(); }
        const uint32_t curA = base + (it & 1) * STG;
        const uint32_t curB = curA + 16384;

        uint32_t af[2][4][4], bf[2][4];
#define LDA(k16, buf)                                                           \
        _Pragma("unroll")                                                       \
        for (int _mt = 0; _mt < 4; _mt++)                                       \
            ldsm4(af[buf][_mt][0], af[buf][_mt][1], af[buf][_mt][2],            \
                  af[buf][_mt][3],                                              \
                  curA + SWZ128((uint32_t)((arow + _mt * 16) * 128 +            \
                                           ((k16) * 16 + aoff) * 2)))
#define LDB(k16, p, buf)                                                        \
        ldsm4(bf[buf][0], bf[buf][1], bf[buf][2], bf[buf][3],                   \
              curB + SWZ128((uint32_t)((brow + (p) * 16) * 128 +                \
                                       ((k16) * 16 + boff) * 2)))
        LDA(0, 0);
        LDB(0, 0, 0);
#pragma unroll
        for (int c8 = 0; c8 < 8; c8++) {
            const int k16 = c8 >> 1, p = c8 & 1;
            const int ba = k16 & 1, bb = c8 & 1;
            if (c8 < 7) LDB((c8 + 1) >> 1, (c8 + 1) & 1, bb ^ 1);
            if (p == 0 && k16 < 3) LDA(k16 + 1, ba ^ 1);
#pragma unroll
            for (int mt = 0; mt < 4; mt++) {
                mma16816(acc[mt][2 * p], af[ba][mt], bf[bb][0], bf[bb][1]);
                mma16816(acc[mt][2 * p + 1], af[ba][mt], bf[bb][2], bf[bb][3]);
            }
        }
#undef LDA
#undef LDB
    }
#undef GEMM_LOAD

#pragma unroll
    for (int mt = 0; mt < 4; mt++) {
        const int row = bm + wr * 64 + mt * 16 + (lane >> 2);
#pragma unroll
        for (int nt = 0; nt < 4; nt++) {
            const int col = bn + wc * 32 + nt * 8 + (lane & 3) * 2;
            if (SPLIT_OUT) {
                uint32_t h, l;
                mkfrag(h, l, acc[mt][nt][0], acc[mt][nt][1]);
                *(uint32_t*)(Ch + (size_t)row * 3072 + col) = h;
                *(uint32_t*)(Cl + (size_t)row * 3072 + col) = l;
                mkfrag(h, l, acc[mt][nt][2], acc[mt][nt][3]);
                *(uint32_t*)(Ch + (size_t)(row + 8) * 3072 + col) = h;
                *(uint32_t*)(Cl + (size_t)(row + 8) * 3072 + col) = l;
            } else {
                float b0v = 0.f, b1v = 0.f;
                if (HAS_BIAS) { b0v = __ldg(&bias[col]); b1v = __ldg(&bias[col + 1]); }
                *(float2*)&C[(size_t)row * NCOL + col] =
                    make_float2(acc[mt][nt][0] + b0v, acc[mt][nt][1] + b1v);
                *(float2*)&C[(size_t)(row + 8) * NCOL + col] =
                    make_float2(acc[mt][nt][2] + b0v, acc[mt][nt][3] + b1v);
            }
        }
    }
}

__global__ __launch_bounds__(256, 2) void k_gemm_qkv(int bm0) {
    gemm_core<true, false, 3072>(g_xs, g_ws, nullptr, g_qkvh, g_qkvl, nullptr, bm0);
}
__global__ __launch_bounds__(256, 2) void k_gemm_proj(const float* __restrict__ bias,
                                                      float* __restrict__ out, int bm0) {
    gemm_core<false, true, 1024>(g_aos, g_wp, out, nullptr, nullptr, bias, bm0);
}

// ---------------- flash attention (bf16x3 split), q-tile 128, 8 warps --------
__global__ __launch_bounds__(256, 2) void k_attn(int batch) {
    extern __shared__ char smraw[];
    const uint32_t base = (smem_u32(smraw) + 1023u) & ~1023u;
    const uint32_t QH = base, QL = base + 16384;
    const uint32_t KV0 = base + 32768;
    const int tid = threadIdx.x, lane = tid & 31, wid = tid >> 5;
    const int head = blockIdx.y, q0 = blockIdx.x * 128;
    const size_t tok0 = (size_t)batch * 2048;
    const int qc = head * 64, kcol = 1024 + qc, vcol = 2048 + qc;
    constexpr float CS = SCALE * LOG2E;

#pragma unroll
    for (int j = 0; j < 4; j++) {
        int idx = tid + j * 256;
        int r = idx >> 3, c = (idx & 7) * 8;
        size_t off = (tok0 + q0 + r) * 3072 + qc + c;
        uint32_t d = SWZ128((uint32_t)(r * 128 + c * 2));
        sts128(QH + d, *(const uint4*)(g_qkvh + off));
        sts128(QL + d, *(const uint4*)(g_qkvl + off));
    }

#define KV_LOAD(stage, t)                                                       \
    do {                                                                        \
        const uint32_t _kb = KV0 + (stage) * 32768;                             \
        const int _kv0 = (t) * 64;                                              \
        _Pragma("unroll")                                                       \
        for (int _j = 0; _j < 2; _j++) {                                        \
            int _idx = tid + _j * 256;                                          \
            int _r = _idx >> 3, _c = (_idx & 7) * 8;                            \
            size_t _ro = (tok0 + _kv0 + _r) * 3072;                             \
            uint32_t _d = SWZ128((uint32_t)(_r * 128 + _c * 2));                \
            cpa16(_kb + _d,         g_qkvh + _ro + kcol + _c);                  \
            cpa16(_kb + 8192 + _d,  g_qkvl + _ro + kcol + _c);                  \
            cpa16(_kb + 16384 + _d, g_qkvh + _ro + vcol + _c);                  \
            cpa16(_kb + 24576 + _d, g_qkvl + _ro + vcol + _c);                  \
        }                                                                       \
    } while (0)

    KV_LOAD(0, 0); CP_COMMIT();
    __syncthreads();

    uint32_t aqh[4][4], aql[4][4];
#pragma unroll
    for (int k = 0; k < 4; k++) {
        int rr = wid * 16 + (lane & 15);
        int cq = k * 16 + ((lane & 16) ? 8 : 0);
        uint32_t d = SWZ128((uint32_t)(rr * 128 + cq * 2));
        ldsm4(aqh[k][0], aqh[k][1], aqh[k][2], aqh[k][3], QH + d);
        ldsm4(aql[k][0], aql[k][1], aql[k][2], aql[k][3], QL + d);
    }

    float o[8][4];
#pragma unroll
    for (int i = 0; i < 8; i++)
#pragma unroll
        for (int j = 0; j < 4; j++) o[i][j] = 0.f;
    float m0 = -1e30f, m1 = -1e30f, l0 = 0.f, l1 = 0.f;

    for (int t = 0; t < 32; t++) {
        CP_WAIT0();
        __syncthreads();
        if (t + 1 < 32) { KV_LOAD((t + 1) & 1, t + 1); CP_COMMIT(); }
        const uint32_t KH = KV0 + (t & 1) * 32768, KL = KH + 8192,
                       VH = KH + 16384, VL = KH + 24576;

        // ---- S = Q K^T (3-term split), LDSM double-buffered ----
        float s[8][4];
#pragma unroll
        for (int i = 0; i < 8; i++)
#pragma unroll
            for (int j = 0; j < 4; j++) s[i][j] = 0.f;
        {
            uint32_t kh[2][4], kl[2][4];
#define LDK(i, buf)                                                             \
            do {                                                                \
                const int _k = (i) >> 2, _p = (i) & 3;                          \
                const int _kb = _k * 16 + ((lane & 8) ? 8 : 0);                 \
                const int _nr = _p * 16 + (lane & 7) + ((lane & 16) ? 8 : 0);   \
                uint32_t _d = SWZ128((uint32_t)(_nr * 128 + _kb * 2));          \
                ldsm4(kh[buf][0], kh[buf][1], kh[buf][2], kh[buf][3], KH + _d); \
                ldsm4(kl[buf][0], kl[buf][1], kl[buf][2], kl[buf][3], KL + _d); \
            } while (0)
            LDK(0, 0);
#pragma unroll
            for (int i = 0; i < 16; i++) {
                const int k = i >> 2, p = i & 3, cb = i & 1;
                if (i < 15) LDK(i + 1, cb ^ 1);
                mma16816(s[2 * p], aqh[k], kh[cb][0], kh[cb][1]);
                mma16816(s[2 * p], aqh[k], kl[cb][0], kl[cb][1]);
                mma16816(s[2 * p], aql[k], kh[cb][0], kh[cb][1]);
                mma16816(s[2 * p + 1], aqh[k], kh[cb][2], kh[cb][3]);
                mma16816(s[2 * p + 1], aqh[k], kl[cb][2], kl[cb][3]);
                mma16816(s[2 * p + 1], aql[k], kh[cb][2], kh[cb][3]);
            }
#undef LDK
        }

        // ---- online softmax in exp2 domain ----
        float mx0 = -1e30f, mx1 = -1e30f;
#pragma unroll
        for (int nt = 0; nt < 8; nt++) {
#pragma unroll
            for (int j = 0; j < 4; j++) s[nt][j] *= CS;
            mx0 = fmaxf(mx0, fmaxf(s[nt][0], s[nt][1]));
            mx1 = fmaxf(mx1, fmaxf(s[nt][2], s[nt][3]));
        }
        mx0 = fmaxf(mx0, __shfl_xor_sync(0xffffffffu, mx0, 1));
        mx0 = fmaxf(mx0, __shfl_xor_sync(0xffffffffu, mx0, 2));
        mx1 = fmaxf(mx1, __shfl_xor_sync(0xffffffffu, mx1, 1));
        mx1 = fmaxf(mx1, __shfl_xor_sync(0xffffffffu, mx1, 2));
        const float mn0 = fmaxf(m0, mx0), mn1 = fmaxf(m1, mx1);
        const float a0 = exp2f(m0 - mn0), a1 = exp2f(m1 - mn1);
        m0 = mn0; m1 = mn1;
        float sum0 = 0.f, sum1 = 0.f;
#pragma unroll
        for (int nt = 0; nt < 8; nt++) {
            s[nt][0] = exp2f(s[nt][0] - mn0);
            s[nt][1] = exp2f(s[nt][1] - mn0);
            s[nt][2] = exp2f(s[nt][2] - mn1);
            s[nt][3] = exp2f(s[nt][3] - mn1);
            sum0 += s[nt][0] + s[nt][1];
            sum1 += s[nt][2] + s[nt][3];
            o[nt][0] *= a0; o[nt][1] *= a0;
            o[nt][2] *= a1; o[nt][3] *= a1;
        }
        sum0 += __shfl_xor_sync(0xffffffffu, sum0, 1);
        sum0 += __shfl_xor_sync(0xffffffffu, sum0, 2);
        sum1 += __shfl_xor_sync(0xffffffffu, sum1, 1);
        sum1 += __shfl_xor_sync(0xffffffffu, sum1, 2);
        l0 = l0 * a0 + sum0;
        l1 = l1 * a1 + sum1;

        // ---- P fragments (hi + residual lo) ----
        uint32_t ph[4][4], pl[4][4];
#pragma unroll
        for (int k = 0; k < 4; k++) {
            mkfrag(ph[k][0], pl[k][0], s[2 * k][0], s[2 * k][1]);
            mkfrag(ph[k][1], pl[k][1], s[2 * k][2], s[2 * k][3]);
            mkfrag(ph[k][2], pl[k][2], s[2 * k + 1][0], s[2 * k + 1][1]);
            mkfrag(ph[k][3], pl[k][3], s[2 * k + 1][2], s[2 * k + 1][3]);
        }

        // ---- O += P V (3-term split), LDSM double-buffered ----
        {
            uint32_t vh[2][4], vl[2][4];
#define LDV(i, buf)                                                             \
            do {                                                                \
                const int _k = (i) >> 2, _p = (i) & 3;                          \
                const int _kvr = _k * 16 + (lane & 7) + ((lane & 8) ? 8 : 0);   \
                const int _dc = _p * 16 + ((lane & 16) ? 8 : 0);                \
                uint32_t _d = SWZ128((uint32_t)(_kvr * 128 + _dc * 2));         \
                ldsm4t(vh[buf][0], vh[buf][1], vh[buf][2], vh[buf][3], VH + _d);\
                ldsm4t(vl[buf][0], vl[buf][1], vl[buf][2], vl[buf][3], VL + _d);\
            } while (0)
            LDV(0, 0);
#pragma unroll
            for (int i = 0; i < 16; i++) {
                const int k = i >> 2, p = i & 3, cb = i & 1;
                if (i < 15) LDV(i + 1, cb ^ 1);
                mma16816(o[2 * p], ph[k], vh[cb][0], vh[cb][1]);
                mma16816(o[2 * p], ph[k], vl[cb][0], vl[cb][1]);
                mma16816(o[2 * p], pl[k], vh[cb][0], vh[cb][1]);
                mma16816(o[2 * p + 1], ph[k], vh[cb][2], vh[cb][3]);
                mma16816(o[2 * p + 1], ph[k], vl[cb][2], vl[cb][3]);
                mma16816(o[2 * p + 1], pl[k], vh[cb][2], vh[cb][3]);
            }
#undef LDV
        }
    }
#undef KV_LOAD

    // ---- normalize + write split [hi|hi|lo] rows of g_aos ----
    const float inv0 = 1.f / l0, inv1 = 1.f / l1;
    const int rq = q0 + wid * 16 + (lane >> 2);
    __nv_bfloat16* d0 = g_aos + (tok0 + rq) * 3072 + head * 64;
    __nv_bfloat16* d1 = d0 + 8 * 3072;
#pragma unroll
    for (int nt = 0; nt < 8; nt++) {
        const int col = nt * 8 + (lane & 3) * 2;
        uint32_t h, l;
        mkfrag(h, l, o[nt][0] * inv0, o[nt][1] * inv0);
        *(uint32_t*)(d0 + col) = h;
        *(uint32_t*)(d0 + 1024 + col) = h;
        *(uint32_t*)(d0 + 2048 + col) = l;
        mkfrag(h, l, o[nt][2] * inv1, o[nt][3] * inv1);
        *(uint32_t*)(d1 + col) = h;
        *(uint32_t*)(d1 + 1024 + col) = h;
        *(uint32_t*)(d1 + 2048 + col) = l;
    }
}

// ---------------- launch: batch-pipelined multi-stream graph -----------------
extern "C" void kernel_launch(void* const* d_in, const int* in_sizes, int n_in,
                              void* d_out, int out_size) {
    (void)in_sizes; (void)n_in; (void)out_size;
    const float* x      = (const float*)d_in[0];
    const float* w_qkv  = (const float*)d_in[1];
    const float* w_proj = (const float*)d_in[2];
    const float* b_proj = (const float*)d_in[3];
    float* out = (float*)d_out;

    static cudaStream_t s1, s2, s3;
    static cudaEvent_t evRoot, evW, evQ[4], evA[4], evDone;
    static bool init = false;
    if (!init) {
        cudaStreamCreateWithFlags(&s1, cudaStreamNonBlocking);
        cudaStreamCreateWithFlags(&s2, cudaStreamNonBlocking);
        cudaStreamCreateWithFlags(&s3, cudaStreamNonBlocking);
        cudaEventCreateWithFlags(&evRoot, cudaEventDisableTiming);
        cudaEventCreateWithFlags(&evW, cudaEventDisableTiming);
        for (int b = 0; b < 4; b++) {
            cudaEventCreateWithFlags(&evQ[b], cudaEventDisableTiming);
            cudaEventCreateWithFlags(&evA[b], cudaEventDisableTiming);
        }
        cudaEventCreateWithFlags(&evDone, cudaEventDisableTiming);
        cudaFuncSetAttribute(k_gemm_qkv, cudaFuncAttributeMaxDynamicSharedMemorySize, 66560);
        cudaFuncSetAttribute(k_gemm_proj, cudaFuncAttributeMaxDynamicSharedMemorySize, 66560);
        cudaFuncSetAttribute(k_attn, cudaFuncAttributeMaxDynamicSharedMemorySize, 99328);
        init = true;
    }

    // fork three streams off the capture-origin (default) stream
    cudaEventRecord(evRoot, 0);
    cudaStreamWaitEvent(s1, evRoot, 0);
    cudaStreamWaitEvent(s2, evRoot, 0);
    cudaStreamWaitEvent(s3, evRoot, 0);

    k_split_x<<<16384, 256, 0, s1>>>(x);
    k_split_wqkv<<<6144, 256, 0, s2>>>(w_qkv);
    k_split_wproj<<<2048, 256, 0, s3>>>(w_proj);

    cudaEventRecord(evW, s2);
    cudaStreamWaitEvent(s1, evW, 0);      // qkv needs x-split (s1) + wqkv-split (s2)

    for (int b = 0; b < 4; b++) {
        k_gemm_qkv<<<dim3(24, 16), 256, 66560, s1>>>(b * 2048);
        cudaEventRecord(evQ[b], s1);
        cudaStreamWaitEvent(s2, evQ[b], 0);
        k_attn<<<dim3(16, 16), 256, 99328, s2>>>(b);
        cudaEventRecord(evA[b], s2);
        cudaStreamWaitEvent(s3, evA[b], 0);
        k_gemm_proj<<<dim3(8, 16), 256, 66560, s3>>>(b_proj, out, b * 2048);
    }

    // join back to the capture-origin stream
    cudaEventRecord(evDone, s3);
    cudaStreamWaitEvent(0, evDone, 0);
}

// round 8
// speedup vs baseline: 1.0036x; 1.0036x over previous
#include <cuda_runtime.h>
#include <cuda_bf16.h>
#include <cstdint>

#define SCALE 0.125f
#define LOG2E 1.4426950408889634f
#define SWZ128(o) ((o) ^ (((o) >> 3) & 0x70))

// ---------------- scratch: 2-plane (hi, lo) bf16 arrays ----------------------
#define XPLANE   8388608u    // 8192*1024
#define WQPLANE  3145728u    // 3072*1024
#define WPPLANE  1048576u    // 1024*1024
#define AOPLANE  8388608u
#define QKVPLANE 25165824u   // 8192*3072
__device__ __nv_bfloat16 g_x2[16777216];    // x       hi|lo planes, 8192x1024
__device__ __nv_bfloat16 g_wq2[6291456];    // w_qkv   hi|lo planes, 3072x1024
__device__ __nv_bfloat16 g_wp2[2097152];    // w_proj  hi|lo planes, 1024x1024
__device__ __nv_bfloat16 g_ao2[16777216];   // attnout hi|lo planes, 8192x1024
__device__ __nv_bfloat16 g_qkv2[50331648];  // qkv     hi|lo planes, 8192x3072

// ---------------- helpers ----------------
__device__ __forceinline__ uint32_t smem_u32(const void* p) {
    uint32_t a;
    asm("{ .reg .u64 t; cvta.to.shared.u64 t, %1; cvt.u32.u64 %0, t; }" : "=r"(a) : "l"(p));
    return a;
}
__device__ __forceinline__ void ldsm4(uint32_t& r0, uint32_t& r1, uint32_t& r2,
                                      uint32_t& r3, uint32_t a) {
    asm volatile("ldmatrix.sync.aligned.m8n8.x4.shared.b16 {%0,%1,%2,%3},[%4];"
                 : "=r"(r0), "=r"(r1), "=r"(r2), "=r"(r3) : "r"(a));
}
__device__ __forceinline__ void ldsm4t(uint32_t& r0, uint32_t& r1, uint32_t& r2,
                                       uint32_t& r3, uint32_t a) {
    asm volatile("ldmatrix.sync.aligned.m8n8.x4.trans.shared.b16 {%0,%1,%2,%3},[%4];"
                 : "=r"(r0), "=r"(r1), "=r"(r2), "=r"(r3) : "r"(a));
}
__device__ __forceinline__ void sts128(uint32_t a, uint4 v) {
    asm volatile("st.shared.v4.b32 [%0], {%1,%2,%3,%4};"
                 :: "r"(a), "r"(v.x), "r"(v.y), "r"(v.z), "r"(v.w) : "memory");
}
__device__ __forceinline__ void cpa16(uint32_t dst, const void* src) {
    asm volatile("cp.async.cg.shared.global [%0], [%1], 16;" :: "r"(dst), "l"(src)
                 : "memory");
}
#define CP_COMMIT() asm volatile("cp.async.commit_group;" ::: "memory")
#define CP_WAIT0()  asm volatile("cp.async.wait_group 0;" ::: "memory")
__device__ __forceinline__ void mma16816(float* c, const uint32_t* a,
                                         uint32_t b0, uint32_t b1) {
    asm volatile(
        "mma.sync.aligned.m16n8k16.row.col.f32.bf16.bf16.f32 "
        "{%0,%1,%2,%3},{%4,%5,%6,%7},{%8,%9},{%0,%1,%2,%3};"
        : "+f"(c[0]), "+f"(c[1]), "+f"(c[2]), "+f"(c[3])
        : "r"(a[0]), "r"(a[1]), "r"(a[2]), "r"(a[3]), "r"(b0), "r"(b1));
}
__device__ __forceinline__ uint32_t cvt2(float f0, float f1) {
    uint32_t r;
    asm("cvt.rn.bf16x2.f32 %0, %1, %2;" : "=r"(r) : "f"(f1), "f"(f0));
    return r;
}
__device__ __forceinline__ void mkfrag(uint32_t& h, uint32_t& l, float f0, float f1) {
    h = cvt2(f0, f1);
    float r0 = f0 - __uint_as_float(h << 16);
    float r1 = f1 - __uint_as_float(h & 0xffff0000u);
    l = cvt2(r0, r1);
}

// ---------------- split kernels: f32 -> hi plane + lo plane ------------------
__device__ __forceinline__ void split_core(const float* __restrict__ src,
                                           __nv_bfloat16* __restrict__ dst,
                                           uint32_t plane) {
    long i = (long)blockIdx.x * 256 + threadIdx.x;
    long r = i >> 9;
    int k2 = (int)(i & 511) << 1;
    float2 v = *(const float2*)(src + r * 1024 + k2);
    __nv_bfloat16 h0 = __float2bfloat16(v.x), h1 = __float2bfloat16(v.y);
    __nv_bfloat16 l0 = __float2bfloat16(v.x - __bfloat162float(h0));
    __nv_bfloat16 l1 = __float2bfloat16(v.y - __bfloat162float(h1));
    __nv_bfloat16* base = dst + r * 1024 + k2;
    *(__nv_bfloat162*)(base) = __halves2bfloat162(h0, h1);
    *(__nv_bfloat162*)(base + plane) = __halves2bfloat162(l0, l1);
}
__global__ __launch_bounds__(256) void k_split_x(const float* __restrict__ s) {
    split_core(s, g_x2, XPLANE);
}
__global__ __launch_bounds__(256) void k_split_wqkv(const float* __restrict__ s) {
    split_core(s, g_wq2, WQPLANE);
}
__global__ __launch_bounds__(256) void k_split_wproj(const float* __restrict__ s) {
    split_core(s, g_wp2, WPPLANE);
}

// ---------------- mma.sync GEMM, 2-plane 3-chain, BK=32, 2-stage -------------
// C[M,N] = A[M,1024]*B[N,1024]^T in split precision (AhBh + AhBl + AlBh).
// smem row (128B) = [hi 64B | lo 64B] of one k32 chunk. SW128 swizzle.
template <bool SPLIT_OUT, bool HAS_BIAS, int NCOL, uint32_t PA, uint32_t PB>
__device__ __forceinline__ void gemm_core(const __nv_bfloat16* __restrict__ A,
                                          const __nv_bfloat16* __restrict__ B,
                                          float* __restrict__ C,
                                          __nv_bfloat16* __restrict__ Ch,
                                          const float* __restrict__ bias) {
    constexpr int KT = 1024;
    constexpr int STG = 32768;                 // A 16K + B 16K per stage
    extern __shared__ char smraw[];
    const uint32_t base = (smem_u32(smraw) + 1023u) & ~1023u;
    const int tid = threadIdx.x, lane = tid & 31, wid = tid >> 5;
    const int wr = wid >> 2, wc = wid & 3;
    const int bm = blockIdx.y * 128, bn = blockIdx.x * 128;

    float acc[4][4][4];
#pragma unroll
    for (int i = 0; i < 4; i++)
#pragma unroll
        for (int j = 0; j < 4; j++)
#pragma unroll
            for (int q = 0; q < 4; q++) acc[i][j][q] = 0.f;

    // loader mapping: thread -> (row r0 + j*32, chunk c). c<4: hi plane cols
    // (c*8); c>=4: lo plane cols ((c-4)*8).
    const int r0 = tid >> 3, c = tid & 7;
    const __nv_bfloat16* Ap =
        A + (size_t)(bm + r0) * KT + (c & 3) * 8 + ((c & 4) ? PA : 0);
    const __nv_bfloat16* Bp =
        B + (size_t)(bn + r0) * KT + (c & 3) * 8 + ((c & 4) ? PB : 0);

#define GEMM_LOAD(stage, it)                                                    \
    do {                                                                        \
        const int _k0 = (it) * 32;                                              \
        const uint32_t _sa = base + (stage) * STG;                              \
        const uint32_t _sb = _sa + 16384;                                       \
        _Pragma("unroll")                                                       \
        for (int _j = 0; _j < 4; _j++) {                                        \
            const uint32_t _d = SWZ128((uint32_t)((r0 + _j * 32) * 128 + c * 16)); \
            cpa16(_sa + _d, Ap + (size_t)_j * 32 * KT + _k0);                   \
            cpa16(_sb + _d, Bp + (size_t)_j * 32 * KT + _k0);                   \
        }                                                                       \
    } while (0)

    GEMM_LOAD(0, 0); CP_COMMIT();

    const int arow = wr * 64 + (lane & 15);
    const int aoffb = (lane & 16) ? 16 : 0;    // byte offset of k within chunk
    const int brow = wc * 32 + (lane & 7) + ((lane & 16) ? 8 : 0);
    const int boffb = (lane & 8) ? 16 : 0;

    for (int it = 0; it < 32; it++) {
        CP_WAIT0();
        __syncthreads();
        if (it + 1 < 32) { GEMM_LOAD((it + 1) & 1, it + 1); CP_COMMIT(); }
        const uint32_t curA = base + (it & 1) * STG;
        const uint32_t curB = curA + 16384;

#pragma unroll
        for (int k16 = 0; k16 < 2; k16++) {
            uint32_t ah[4][4], al[4][4];
#pragma unroll
            for (int mt = 0; mt < 4; mt++) {
                const uint32_t ra = (uint32_t)((arow + mt * 16) * 128 +
                                               k16 * 32 + aoffb);
                ldsm4(ah[mt][0], ah[mt][1], ah[mt][2], ah[mt][3],
                      curA + SWZ128(ra));
                ldsm4(al[mt][0], al[mt][1], al[mt][2], al[mt][3],
                      curA + SWZ128(ra + 64));
            }
#pragma unroll
            for (int p = 0; p < 2; p++) {
                const uint32_t rb = (uint32_t)((brow + p * 16) * 128 +
                                               k16 * 32 + boffb);
                uint32_t bh[4], bl[4];
                ldsm4(bh[0], bh[1], bh[2], bh[3], curB + SWZ128(rb));
                ldsm4(bl[0], bl[1], bl[2], bl[3], curB + SWZ128(rb + 64));
#pragma unroll
                for (int mt = 0; mt < 4; mt++) {
                    mma16816(acc[mt][2 * p], ah[mt], bh[0], bh[1]);
                    mma16816(acc[mt][2 * p], ah[mt], bl[0], bl[1]);
                    mma16816(acc[mt][2 * p], al[mt], bh[0], bh[1]);
                    mma16816(acc[mt][2 * p + 1], ah[mt], bh[2], bh[3]);
                    mma16816(acc[mt][2 * p + 1], ah[mt], bl[2], bl[3]);
                    mma16816(acc[mt][2 * p + 1], al[mt], bh[2], bh[3]);
                }
            }
        }
    }
#undef GEMM_LOAD

#pragma unroll
    for (int mt = 0; mt < 4; mt++) {
        const int row = bm + wr * 64 + mt * 16 + (lane >> 2);
#pragma unroll
        for (int nt = 0; nt < 4; nt++) {
            const int col = bn + wc * 32 + nt * 8 + (lane & 3) * 2;
            if (SPLIT_OUT) {
                uint32_t h, l;
                mkfrag(h, l, acc[mt][nt][0], acc[mt][nt][1]);
                *(uint32_t*)(Ch + (size_t)row * NCOL + col) = h;
                *(uint32_t*)(Ch + QKVPLANE + (size_t)row * NCOL + col) = l;
                mkfrag(h, l, acc[mt][nt][2], acc[mt][nt][3]);
                *(uint32_t*)(Ch + (size_t)(row + 8) * NCOL + col) = h;
                *(uint32_t*)(Ch + QKVPLANE + (size_t)(row + 8) * NCOL + col) = l;
            } else {
                float b0v = 0.f, b1v = 0.f;
                if (HAS_BIAS) { b0v = __ldg(&bias[col]); b1v = __ldg(&bias[col + 1]); }
                *(float2*)&C[(size_t)row * NCOL + col] =
                    make_float2(acc[mt][nt][0] + b0v, acc[mt][nt][1] + b1v);
                *(float2*)&C[(size_t)(row + 8) * NCOL + col] =
                    make_float2(acc[mt][nt][2] + b0v, acc[mt][nt][3] + b1v);
            }
        }
    }
}

__global__ __launch_bounds__(256, 2) void k_gemm_qkv() {
    gemm_core<true, false, 3072, XPLANE, WQPLANE>(g_x2, g_wq2, nullptr, g_qkv2,
                                                  nullptr);
}
__global__ __launch_bounds__(256, 2) void k_gemm_proj(const float* __restrict__ bias,
                                                      float* __restrict__ out) {
    gemm_core<false, true, 1024, AOPLANE, WPPLANE>(g_ao2, g_wp2, out, nullptr,
                                                   bias);
}

// ---------------- flash attention (bf16x3 split), q-tile 128, 8 warps --------
__global__ __launch_bounds__(256, 2) void k_attn() {
    extern __shared__ char smraw[];
    const uint32_t base = (smem_u32(smraw) + 1023u) & ~1023u;
    const uint32_t QH = base, QL = base + 16384;
    const uint32_t KV0 = base + 32768;
    const int tid = threadIdx.x, lane = tid & 31, wid = tid >> 5;
    const int bh = blockIdx.y, q0 = blockIdx.x * 128;
    const size_t tok0 = (size_t)(bh >> 4) * 2048;
    const int qc = (bh & 15) * 64, kcol = 1024 + qc, vcol = 2048 + qc;
    constexpr float CS = SCALE * LOG2E;
    const __nv_bfloat16* qkvh = g_qkv2;
    const __nv_bfloat16* qkvl = g_qkv2 + QKVPLANE;

#pragma unroll
    for (int j = 0; j < 4; j++) {
        int idx = tid + j * 256;
        int r = idx >> 3, cc = (idx & 7) * 8;
        size_t off = (tok0 + q0 + r) * 3072 + qc + cc;
        uint32_t d = SWZ128((uint32_t)(r * 128 + cc * 2));
        sts128(QH + d, *(const uint4*)(qkvh + off));
        sts128(QL + d, *(const uint4*)(qkvl + off));
    }

#define KV_LOAD(stage, t)                                                       \
    do {                                                                        \
        const uint32_t _kb = KV0 + (stage) * 32768;                             \
        const int _kv0 = (t) * 64;                                              \
        _Pragma("unroll")                                                       \
        for (int _j = 0; _j < 2; _j++) {                                        \
            int _idx = tid + _j * 256;                                          \
            int _r = _idx >> 3, _c = (_idx & 7) * 8;                            \
            size_t _ro = (tok0 + _kv0 + _r) * 3072;                             \
            uint32_t _d = SWZ128((uint32_t)(_r * 128 + _c * 2));                \
            cpa16(_kb + _d,         qkvh + _ro + kcol + _c);                    \
            cpa16(_kb + 8192 + _d,  qkvl + _ro + kcol + _c);                    \
            cpa16(_kb + 16384 + _d, qkvh + _ro + vcol + _c);                    \
            cpa16(_kb + 24576 + _d, qkvl + _ro + vcol + _c);                    \
        }                                                                       \
    } while (0)

    KV_LOAD(0, 0); CP_COMMIT();
    __syncthreads();

    uint32_t aqh[4][4], aql[4][4];
#pragma unroll
    for (int k = 0; k < 4; k++) {
        int rr = wid * 16 + (lane & 15);
        int cq = k * 16 + ((lane & 16) ? 8 : 0);
        uint32_t d = SWZ128((uint32_t)(rr * 128 + cq * 2));
        ldsm4(aqh[k][0], aqh[k][1], aqh[k][2], aqh[k][3], QH + d);
        ldsm4(aql[k][0], aql[k][1], aql[k][2], aql[k][3], QL + d);
    }

    float o[8][4];
#pragma unroll
    for (int i = 0; i < 8; i++)
#pragma unroll
        for (int j = 0; j < 4; j++) o[i][j] = 0.f;
    float m0 = -1e30f, m1 = -1e30f, l0 = 0.f, l1 = 0.f;

    for (int t = 0; t < 32; t++) {
        CP_WAIT0();
        __syncthreads();
        if (t + 1 < 32) { KV_LOAD((t + 1) & 1, t + 1); CP_COMMIT(); }
        const uint32_t KH = KV0 + (t & 1) * 32768, KL = KH + 8192,
                       VH = KH + 16384, VL = KH + 24576;

        // ---- S = Q K^T (3-term split), LDSM double-buffered ----
        float s[8][4];
#pragma unroll
        for (int i = 0; i < 8; i++)
#pragma unroll
            for (int j = 0; j < 4; j++) s[i][j] = 0.f;
        {
            uint32_t kh[2][4], kl[2][4];
#define LDK(i, buf)                                                             \
            do {                                                                \
                const int _k = (i) >> 2, _p = (i) & 3;                          \
                const int _kb = _k * 16 + ((lane & 8) ? 8 : 0);                 \
                const int _nr = _p * 16 + (lane & 7) + ((lane & 16) ? 8 : 0);   \
                uint32_t _d = SWZ128((uint32_t)(_nr * 128 + _kb * 2));          \
                ldsm4(kh[buf][0], kh[buf][1], kh[buf][2], kh[buf][3], KH + _d); \
                ldsm4(kl[buf][0], kl[buf][1], kl[buf][2], kl[buf][3], KL + _d); \
            } while (0)
            LDK(0, 0);
#pragma unroll
            for (int i = 0; i < 16; i++) {
                const int k = i >> 2, p = i & 3, cb = i & 1;
                if (i < 15) LDK(i + 1, cb ^ 1);
                mma16816(s[2 * p], aqh[k], kh[cb][0], kh[cb][1]);
                mma16816(s[2 * p], aqh[k], kl[cb][0], kl[cb][1]);
                mma16816(s[2 * p], aql[k], kh[cb][0], kh[cb][1]);
                mma16816(s[2 * p + 1], aqh[k], kh[cb][2], kh[cb][3]);
                mma16816(s[2 * p + 1], aqh[k], kl[cb][2], kl[cb][3]);
                mma16816(s[2 * p + 1], aql[k], kh[cb][2], kh[cb][3]);
            }
#undef LDK
        }

        // ---- online softmax in exp2 domain ----
        float mx0 = -1e30f, mx1 = -1e30f;
#pragma unroll
        for (int nt = 0; nt < 8; nt++) {
#pragma unroll
            for (int j = 0; j < 4; j++) s[nt][j] *= CS;
            mx0 = fmaxf(mx0, fmaxf(s[nt][0], s[nt][1]));
            mx1 = fmaxf(mx1, fmaxf(s[nt][2], s[nt][3]));
        }
        mx0 = fmaxf(mx0, __shfl_xor_sync(0xffffffffu, mx0, 1));
        mx0 = fmaxf(mx0, __shfl_xor_sync(0xffffffffu, mx0, 2));
        mx1 = fmaxf(mx1, __shfl_xor_sync(0xffffffffu, mx1, 1));
        mx1 = fmaxf(mx1, __shfl_xor_sync(0xffffffffu, mx1, 2));
        const float mn0 = fmaxf(m0, mx0), mn1 = fmaxf(m1, mx1);
        const float a0 = exp2f(m0 - mn0), a1 = exp2f(m1 - mn1);
        m0 = mn0; m1 = mn1;
        float sum0 = 0.f, sum1 = 0.f;
#pragma unroll
        for (int nt = 0; nt < 8; nt++) {
            s[nt][0] = exp2f(s[nt][0] - mn0);
            s[nt][1] = exp2f(s[nt][1] - mn0);
            s[nt][2] = exp2f(s[nt][2] - mn1);
            s[nt][3] = exp2f(s[nt][3] - mn1);
            sum0 += s[nt][0] + s[nt][1];
            sum1 += s[nt][2] + s[nt][3];
            o[nt][0] *= a0; o[nt][1] *= a0;
            o[nt][2] *= a1; o[nt][3] *= a1;
        }
        sum0 += __shfl_xor_sync(0xffffffffu, sum0, 1);
        sum0 += __shfl_xor_sync(0xffffffffu, sum0, 2);
        sum1 += __shfl_xor_sync(0xffffffffu, sum1, 1);
        sum1 += __shfl_xor_sync(0xffffffffu, sum1, 2);
        l0 = l0 * a0 + sum0;
        l1 = l1 * a1 + sum1;

        // ---- P fragments (hi + residual lo) ----
        uint32_t ph[4][4], pl[4][4];
#pragma unroll
        for (int k = 0; k < 4; k++) {
            mkfrag(ph[k][0], pl[k][0], s[2 * k][0], s[2 * k][1]);
            mkfrag(ph[k][1], pl[k][1], s[2 * k][2], s[2 * k][3]);
            mkfrag(ph[k][2], pl[k][2], s[2 * k + 1][0], s[2 * k + 1][1]);
            mkfrag(ph[k][3], pl[k][3], s[2 * k + 1][2], s[2 * k + 1][3]);
        }

        // ---- O += P V (3-term split), LDSM double-buffered ----
        {
            uint32_t vh[2][4], vl[2][4];
#define LDV(i, buf)                                                             \
            do {                                                                \
                const int _k = (i) >> 2, _p = (i) & 3;                          \
                const int _kvr = _k * 16 + (lane & 7) + ((lane & 8) ? 8 : 0);   \
                const int _dc = _p * 16 + ((lane & 16) ? 8 : 0);                \
                uint32_t _d = SWZ128((uint32_t)(_kvr * 128 + _dc * 2));         \
                ldsm4t(vh[buf][0], vh[buf][1], vh[buf][2], vh[buf][3], VH + _d);\
                ldsm4t(vl[buf][0], vl[buf][1], vl[buf][2], vl[buf][3], VL + _d);\
            } while (0)
            LDV(0, 0);
#pragma unroll
            for (int i = 0; i < 16; i++) {
                const int k = i >> 2, p = i & 3, cb = i & 1;
                if (i < 15) LDV(i + 1, cb ^ 1);
                mma16816(o[2 * p], ph[k], vh[cb][0], vh[cb][1]);
                mma16816(o[2 * p], ph[k], vl[cb][0], vl[cb][1]);
                mma16816(o[2 * p], pl[k], vh[cb][0], vh[cb][1]);
                mma16816(o[2 * p + 1], ph[k], vh[cb][2], vh[cb][3]);
                mma16816(o[2 * p + 1], ph[k], vl[cb][2], vl[cb][3]);
                mma16816(o[2 * p + 1], pl[k], vh[cb][2], vh[cb][3]);
            }
#undef LDV
        }
    }
#undef KV_LOAD

    // ---- normalize + write hi/lo planes of g_ao2 (1024-wide) ----
    const float inv0 = 1.f / l0, inv1 = 1.f / l1;
    const int rq = q0 + wid * 16 + (lane >> 2);
    __nv_bfloat16* d0 = g_ao2 + (tok0 + rq) * 1024 + (bh & 15) * 64;
    __nv_bfloat16* d1 = d0 + 8 * 1024;
#pragma unroll
    for (int nt = 0; nt < 8; nt++) {
        const int col = nt * 8 + (lane & 3) * 2;
        uint32_t h, l;
        mkfrag(h, l, o[nt][0] * inv0, o[nt][1] * inv0);
        *(uint32_t*)(d0 + col) = h;
        *(uint32_t*)(d0 + AOPLANE + col) = l;
        mkfrag(h, l, o[nt][2] * inv1, o[nt][3] * inv1);
        *(uint32_t*)(d1 + col) = h;
        *(uint32_t*)(d1 + AOPLANE + col) = l;
    }
}

// ---------------- launch (single stream, full grids) -------------------------
extern "C" void kernel_launch(void* const* d_in, const int* in_sizes, int n_in,
                              void* d_out, int out_size) {
    (void)in_sizes; (void)n_in; (void)out_size;
    const float* x      = (const float*)d_in[0];
    const float* w_qkv  = (const float*)d_in[1];
    const float* w_proj = (const float*)d_in[2];
    const float* b_proj = (const float*)d_in[3];
    float* out = (float*)d_out;

    static bool attr_set = false;
    if (!attr_set) {
        cudaFuncSetAttribute(k_gemm_qkv, cudaFuncAttributeMaxDynamicSharedMemorySize, 66560);
        cudaFuncSetAttribute(k_gemm_proj, cudaFuncAttributeMaxDynamicSharedMemorySize, 66560);
        cudaFuncSetAttribute(k_attn, cudaFuncAttributeMaxDynamicSharedMemorySize, 99328);
        attr_set = true;
    }

    k_split_x<<<16384, 256>>>(x);
    k_split_wqkv<<<6144, 256>>>(w_qkv);
    k_split_wproj<<<2048, 256>>>(w_proj);
    k_gemm_qkv<<<dim3(24, 64), 256, 66560>>>();
    k_attn<<<dim3(16, 64), 256, 99328>>>();
    k_gemm_proj<<<dim3(8, 64), 256, 66560>>>(b_proj, out);
}